// round 1
// baseline (speedup 1.0000x reference)
#include <cuda_runtime.h>
#include <cstdint>

// Problem constants (fixed by the dataset)
#define B_    2
#define NH_   8
#define N_    4096
#define D_    64
#define K2_   49

// per row: v tile = D*K2 = 3136 floats = 784 float4
#define V_F4  784
#define THREADS 128

__global__ __launch_bounds__(THREADS)
void sw_attention_av_kernel(const float* __restrict__ q_norm,      // [B,NH,N,D]
                            const float* __restrict__ attn_local,  // [B,NH,N,K2]
                            const float* __restrict__ v_local,     // [B,NH,N,D,K2]
                            const float* __restrict__ tokens,      // [NH,D,K2]
                            const float* __restrict__ bias,        // [NH,N,K2]
                            float* __restrict__ out)               // [B,NH,N,D]
{
    const int row = blockIdx.x;              // b*NH*N + h*N + n
    const int t   = threadIdx.x;
    const int h   = (row >> 12) & (NH_ - 1); // N_=4096 => row/4096 % 8
    const int n   = row & (N_ - 1);

    __shared__ float  s_q[D_];
    __shared__ float  s_attn[K2_];
    __shared__ float4 s_v[V_F4];

    // ---- Phase 0: issue the big streaming v loads FIRST (register-buffered)
    const float4* vrow = reinterpret_cast<const float4*>(v_local) + (size_t)row * V_F4;
    float4 r[7];
#pragma unroll
    for (int i = 0; i < 6; i++)
        r[i] = vrow[t + THREADS * i];
    if (t < V_F4 - 6 * THREADS)              // 784 - 768 = 16 remaining
        r[6] = vrow[t + 6 * THREADS];

    // q row -> smem
    if (t < D_)
        s_q[t] = q_norm[(size_t)row * D_ + t];
    __syncthreads();

    // ---- Phase 1: attn[k] = q . tokens[:,k] + bias + attn_local  (overlaps v loads)
    if (t < K2_) {
        const float* tk = tokens + h * (D_ * K2_) + t;   // stride K2_ along d
        float a = 0.f;
#pragma unroll
        for (int d = 0; d < D_; d++)
            a = fmaf(s_q[d], tk[d * K2_], a);
        a += bias[((size_t)h * N_ + n) * K2_ + t];
        a += attn_local[(size_t)row * K2_ + t];
        s_attn[t] = a;
    }

    // ---- Phase 2: spill v registers to smem
#pragma unroll
    for (int i = 0; i < 6; i++)
        s_v[t + THREADS * i] = r[i];
    if (t < V_F4 - 6 * THREADS)
        s_v[t + 6 * THREADS] = r[6];
    __syncthreads();

    // ---- Phase 3: out[d] = sum_k attn[k] * v[d,k]
    if (t < D_) {
        const float* vd = reinterpret_cast<const float*>(s_v) + t * K2_;
        float acc = 0.f;
#pragma unroll
        for (int k = 0; k < K2_; k++)
            acc = fmaf(s_attn[k], vd[k], acc);
        out[(size_t)row * D_ + t] = acc;
    }
}

extern "C" void kernel_launch(void* const* d_in, const int* in_sizes, int n_in,
                              void* d_out, int out_size)
{
    const float* q_norm     = (const float*)d_in[0];
    const float* attn_local = (const float*)d_in[1];
    const float* v_local    = (const float*)d_in[2];
    const float* tokens     = (const float*)d_in[3];
    const float* bias       = (const float*)d_in[4];
    float* out = (float*)d_out;

    const int rows = B_ * NH_ * N_;          // 65536
    sw_attention_av_kernel<<<rows, THREADS>>>(q_norm, attn_local, v_local,
                                              tokens, bias, out);
}

// round 2
// speedup vs baseline: 1.7941x; 1.7941x over previous
#include <cuda_runtime.h>
#include <cstdint>

// Problem constants (fixed by the dataset)
#define B_    2
#define NH_   8
#define N_    4096
#define D_    64
#define K2_   49
#define V_F4  784          // D*K2 floats / 4 = 3136/4
#define THREADS 128
#define ROWS  8            // rows per CTA (8 | 4096 so h is constant per CTA)

__device__ __forceinline__ uint32_t smem_u32(const void* p) {
    return (uint32_t)__cvta_generic_to_shared(p);
}
__device__ __forceinline__ void cp16(uint32_t dst, const void* src) {
    // .cg => L2 only; v_local is streaming (zero reuse), keep L1 for tokens
    asm volatile("cp.async.cg.shared.global [%0], [%1], 16;\n" :: "r"(dst), "l"(src));
}
__device__ __forceinline__ void cp4(uint32_t dst, const void* src) {
    asm volatile("cp.async.ca.shared.global [%0], [%1], 4;\n" :: "r"(dst), "l"(src));
}
__device__ __forceinline__ void cp_commit() {
    asm volatile("cp.async.commit_group;\n" ::: "memory");
}
template <int NPend>
__device__ __forceinline__ void cp_wait() {
    asm volatile("cp.async.wait_group %0;\n" :: "n"(NPend) : "memory");
}

struct __align__(16) Stage {
    float4 v[V_F4];        // 12544 B
    float  q[D_];          // 256 B
    float  al[K2_];        // 196 B
    float  b[K2_];         // 196 B
    float  pad[2];         // keep 16B alignment of array of Stage
};

__global__ __launch_bounds__(THREADS)
void sw_attention_av_pipe(const float* __restrict__ q_norm,      // [B,NH,N,D]
                          const float* __restrict__ attn_local,  // [B,NH,N,K2]
                          const float* __restrict__ v_local,     // [B,NH,N,D,K2]
                          const float* __restrict__ tokens,      // [NH,D,K2]
                          const float* __restrict__ bias,        // [NH,N,K2]
                          float* __restrict__ out)               // [B,NH,N,D]
{
    __shared__ Stage st[2];
    __shared__ float s_attn[K2_];

    const int t    = threadIdx.x;
    const int row0 = blockIdx.x * ROWS;
    const int h    = (row0 >> 12) & (NH_ - 1);
    const float* tok_h = tokens + h * (D_ * K2_);

    // ---- producer: stage a full row (v + q + attn_local + bias) via cp.async
    auto prefetch = [&](int s, int row) {
        const float4* vrow = reinterpret_cast<const float4*>(v_local) + (size_t)row * V_F4;
        uint32_t vdst = smem_u32(st[s].v);
#pragma unroll
        for (int i = 0; i < 6; i++)
            cp16(vdst + (uint32_t)(t + THREADS * i) * 16u, vrow + t + THREADS * i);
        if (t < V_F4 - 6 * THREADS)                         // 16 leftover float4
            cp16(vdst + (uint32_t)(t + 6 * THREADS) * 16u, vrow + t + 6 * THREADS);

        if (t < D_ / 4)
            cp16(smem_u32(st[s].q) + (uint32_t)t * 16u,
                 reinterpret_cast<const float4*>(q_norm + (size_t)row * D_) + t);

        if (t < K2_) {
            const int n = row & (N_ - 1);
            cp4(smem_u32(st[s].al) + (uint32_t)t * 4u, attn_local + (size_t)row * K2_ + t);
            cp4(smem_u32(st[s].b)  + (uint32_t)t * 4u, bias + ((size_t)h * N_ + n) * K2_ + t);
        }
        cp_commit();
    };

    prefetch(0, row0);

    for (int r = 0; r < ROWS; r++) {
        if (r + 1 < ROWS) {
            prefetch((r + 1) & 1, row0 + r + 1);   // keep the DRAM stream flowing
            cp_wait<1>();                           // stage r's group is complete
        } else {
            cp_wait<0>();
        }
        __syncthreads();

        const Stage& S = st[r & 1];

        // ---- attn[k] = q . tokens[:,k] + bias + attn_local   (tokens: L1-hot)
        if (t < K2_) {
            const float* tk = tok_h + t;
            float a = 0.f;
#pragma unroll
            for (int d = 0; d < D_; d++)
                a = fmaf(S.q[d], __ldg(tk + d * K2_), a);
            s_attn[t] = a + S.b[t] + S.al[t];
        }
        __syncthreads();

        // ---- out[d] = sum_k attn[k] * v[d,k]   (stride-49 smem: conflict-free)
        if (t < D_) {
            const float* vd = reinterpret_cast<const float*>(S.v) + t * K2_;
            float acc = 0.f;
#pragma unroll
            for (int k = 0; k < K2_; k++)
                acc = fmaf(s_attn[k], vd[k], acc);
            out[(size_t)(row0 + r) * D_ + t] = acc;
        }

        // readers of stage (r&1) must finish before iteration r+1 overwrites it
        __syncthreads();
    }
}

extern "C" void kernel_launch(void* const* d_in, const int* in_sizes, int n_in,
                              void* d_out, int out_size)
{
    const float* q_norm     = (const float*)d_in[0];
    const float* attn_local = (const float*)d_in[1];
    const float* v_local    = (const float*)d_in[2];
    const float* tokens     = (const float*)d_in[3];
    const float* bias       = (const float*)d_in[4];
    float* out = (float*)d_out;

    const int blocks = (B_ * NH_ * N_) / ROWS;   // 8192
    sw_attention_av_pipe<<<blocks, THREADS>>>(q_norm, attn_local, v_local,
                                              tokens, bias, out);
}